// round 8
// baseline (speedup 1.0000x reference)
#include <cuda_runtime.h>
#include <cstdint>

#define BB 16
#define QL 32
#define TN 10
#define AL 10
#define EE 300
#define HH 256
#define NJOB (BB * TN)
#define NPAIR (NJOB / 2)
#define GRID 148
#define NEGV -10000000000.0f

#define QP 308    // q_emb smem row stride
#define AP 304    // aw3 smem row stride

// ---- smem layout (floats); prep and gemm regions are phase-disjoint ----
#define OFF_W     0       // sim_w w1,w2,w3 : 900
#define OFF_QE    900     // q_emb [32][308] = 9856
#define OFF_AW3   10756   // aw3 [10][304] = 3040
#define OFF_ATT   13796   // 320
#define OFF_ATTS  14116   // 320
#define OFF_QW2   14436
#define OFF_QM    14468
#define OFF_AW1   14500
#define OFF_AM    14516   // ends 14532
// gemm phase:
#define OFF_STAGE 0       // 2 jobs x 600 x 12 = 14400 floats
#define OFF_PART  14400   // 10240 ull = 20480 floats
#define OFF_RED   34880   // 16
#define OFF_BC    34896   // broadcast (ints)
#define SMEM_FLOATS 34904
#define SMEM_BYTES (SMEM_FLOATS * 4)

__device__ float    g_encin[NJOB * 6000];   // [job][a:10][e:600], 3.84 MB
__device__ float    g_maxat[NJOB * QL];
__device__ float    g_shalf[2][NJOB];
__device__ unsigned g_flag[NJOB];
__device__ unsigned g_pctr = 0, g_gctr = 0, g_done = 0;

__device__ __forceinline__ void fma_f32x2(unsigned long long& acc,
                                          unsigned long long a,
                                          unsigned long long b)
{
    asm("fma.rn.f32x2 %0, %1, %2, %0;" : "+l"(acc) : "l"(a), "l"(b));
}

__device__ __forceinline__ unsigned long long pack2(float v)
{
    unsigned long long r;
    uint32_t u = __float_as_uint(v);
    asm("mov.b64 %0, {%1, %1};" : "=l"(r) : "r"(u));
    return r;
}

__global__ void __launch_bounds__(512)
topic_persist(const int* __restrict__ q, const int* __restrict__ alia,
              const float* __restrict__ els, const float* __restrict__ elo,
              const float* __restrict__ cate, const float* __restrict__ emb,
              const float* __restrict__ sim_w, const float* __restrict__ sim_b,
              const float* __restrict__ enc_w, const float* __restrict__ enc_b,
              const float* __restrict__ qlin_w, const float* __restrict__ qlin_b,
              const float* __restrict__ cls_w, const float* __restrict__ cls_b,
              float* __restrict__ out)
{
    extern __shared__ float sm[];
    int* bc = (int*)(sm + OFF_BC);

    const int tid  = threadIdx.x;
    const int lane = tid & 31;
    const int wid  = tid >> 5;

    const float simb = sim_b[0];

    // sim_w -> smem once; persists across all prep items
    for (int i = tid; i < 3 * EE; i += 512) sm[OFF_W + i] = sim_w[i];

    float* w1      = sm + OFF_W;
    float* w2      = w1 + EE;
    float* w3      = w2 + EE;
    float* q_emb   = sm + OFF_QE;
    float* aw3     = sm + OFF_AW3;
    float* atten   = sm + OFF_ATT;
    float* attensm = sm + OFF_ATTS;
    float* qW2     = sm + OFF_QW2;
    float* qmaskS  = sm + OFF_QM;
    float* aW1     = sm + OFF_AW1;
    float* amaskS  = sm + OFF_AM;

    // ================= PREP work loop =================
    for (;;) {
        __syncthreads();
        if (tid == 0) bc[0] = (int)atomicAdd(&g_pctr, 1u);
        __syncthreads();
        const int job = bc[0];
        if (job >= NJOB) break;
        const int b = job / TN;
        float* gje = g_encin + (size_t)job * 6000;

        // ---- q rows: gather + normalize + qW2 dot (warp per row) ----
        for (int j = wid; j < QL; j += 16) {
            int idx = q[b * QL + j];
            float x[10];
            float ss = 0.f;
            #pragma unroll
            for (int i = 0; i < 10; i++) {
                int e = lane + 32 * i;
                float v = (e < EE) ? emb[(size_t)idx * EE + e] : 0.f;
                x[i] = v;
                ss += v * v;
            }
            #pragma unroll
            for (int o = 16; o; o >>= 1) ss += __shfl_xor_sync(0xffffffffu, ss, o);
            float scale = (idx == 0) ? 0.f : 1.f / fmaxf(sqrtf(ss), 1e-12f);
            float dot = 0.f;
            #pragma unroll
            for (int i = 0; i < 10; i++) {
                int e = lane + 32 * i;
                float v = x[i] * scale;
                if (e < EE) {
                    q_emb[j * QP + e] = v;
                    dot += v * w2[e];
                } else if (e < QP) {
                    q_emb[j * QP + e] = 0.f;
                }
            }
            #pragma unroll
            for (int o = 16; o; o >>= 1) dot += __shfl_xor_sync(0xffffffffu, dot, o);
            if (lane == 0) {
                qW2[j]    = dot;
                qmaskS[j] = (idx != 0) ? 1.f : 0.f;
            }
        }

        // ---- alias rows (warps 0..9): normalize, aw3 smem, raw -> g_encin ----
        if (wid < AL) {
            int a = wid;
            int idx = alia[job * AL + a];
            float x[10];
            float ss = 0.f;
            #pragma unroll
            for (int i = 0; i < 10; i++) {
                int e = lane + 32 * i;
                float v = (e < EE) ? emb[(size_t)idx * EE + e] : 0.f;
                x[i] = v;
                ss += v * v;
            }
            #pragma unroll
            for (int o = 16; o; o >>= 1) ss += __shfl_xor_sync(0xffffffffu, ss, o);
            float scale = (idx == 0) ? 0.f : 1.f / fmaxf(sqrtf(ss), 1e-12f);
            float dot = 0.f;
            #pragma unroll
            for (int i = 0; i < 10; i++) {
                int e = lane + 32 * i;
                float v = x[i] * scale;
                if (e < EE) {
                    aw3[a * AP + e] = v * w3[e];
                    gje[a * 600 + 300 + e] = v;        // coalesced along e
                    dot += v * w1[e];
                } else if (e < AP) {
                    aw3[a * AP + e] = 0.f;
                }
            }
            #pragma unroll
            for (int o = 16; o; o >>= 1) dot += __shfl_xor_sync(0xffffffffu, dot, o);
            if (lane == 0) {
                aW1[a]    = dot;
                amaskS[a] = (idx != 0) ? 1.f : 0.f;
            }
        }
        __syncthreads();

        // ---- attention: warp = a, lane = q, float4 over e ----
        if (wid < AL) {
            int a = wid, qi = lane;
            const float4* qe = reinterpret_cast<const float4*>(q_emb + qi * QP);
            const float4* ar = reinterpret_cast<const float4*>(aw3 + a * AP);
            float d = 0.f;
            #pragma unroll 5
            for (int c = 0; c < 75; c++) {
                float4 qv = qe[c];
                float4 av = ar[c];
                d += av.x * qv.x + av.y * qv.y + av.z * qv.z + av.w * qv.w;
            }
            float val = aW1[a] + qW2[qi] + d + simb;
            float m = amaskS[a] * qmaskS[qi];
            atten[a * QL + qi] = m * val + (1.f - m) * NEGV;
        }
        __syncthreads();

        // ---- softmax per alias row + cross-a max ----
        if (wid < AL) {
            int a = wid;
            float v = atten[a * QL + lane];
            float mx = v;
            #pragma unroll
            for (int o = 16; o; o >>= 1) mx = fmaxf(mx, __shfl_xor_sync(0xffffffffu, mx, o));
            float ex = expf(v - mx);
            float s = ex;
            #pragma unroll
            for (int o = 16; o; o >>= 1) s += __shfl_xor_sync(0xffffffffu, s, o);
            attensm[a * QL + lane] = ex / s;
        }
        if (wid == 10) {
            float mx = atten[lane];
            #pragma unroll
            for (int a = 1; a < AL; a++) mx = fmaxf(mx, atten[a * QL + lane]);
            g_maxat[job * QL + lane] = mx;
        }
        __syncthreads();

        // ---- alig -> g_encin[a][0..299] (float4 along e, coalesced) ----
        for (int p = tid; p < AL * 75; p += 512) {
            int a = p / 75, c = p - a * 75;
            const float* as = attensm + a * QL;
            float4 acc = make_float4(0.f, 0.f, 0.f, 0.f);
            #pragma unroll
            for (int qi = 0; qi < QL; qi++) {
                float s = as[qi];
                float4 qv = *reinterpret_cast<const float4*>(q_emb + qi * QP + c * 4);
                acc.x += s * qv.x; acc.y += s * qv.y; acc.z += s * qv.z; acc.w += s * qv.w;
            }
            *reinterpret_cast<float4*>(gje + a * 600 + 4 * c) = acc;
        }

        // release: make g_encin visible, then raise flag
        __threadfence();
        __syncthreads();
        if (tid == 0) g_flag[job] = 1u;
    }

    // ================= GEMM work loop =================
    for (;;) {
        __syncthreads();
        if (tid == 0) bc[0] = (int)atomicAdd(&g_gctr, 1u);
        __syncthreads();
        const int itm = bc[0];
        if (itm >= 2 * NPAIR) break;
        const int jp = itm >> 1;
        const int hf = itm & 1;
        const int j0 = 2 * jp, j1 = 2 * jp + 1;

        if (tid == 0) {
            volatile unsigned* vf = g_flag;
            while (vf[j0] == 0u) __nanosleep(64);
            while (vf[j1] == 0u) __nanosleep(64);
            __threadfence();   // acquire
        }
        __syncthreads();

        // stage both jobs' enc_in with transpose: [a][600] -> rows [e][12]
        {
            const float4* s0 = reinterpret_cast<const float4*>(g_encin + (size_t)j0 * 6000);
            const float4* s1 = reinterpret_cast<const float4*>(g_encin + (size_t)j1 * 6000);
            for (int i = tid; i < 1500; i += 512) {
                float4 v = s0[i];
                int a = i / 150, c = i - a * 150;
                float* d = sm + OFF_STAGE + (4 * c) * 12 + a;
                d[0] = v.x; d[12] = v.y; d[24] = v.z; d[36] = v.w;
            }
            for (int i = tid; i < 1500; i += 512) {
                float4 v = s1[i];
                int a = i / 150, c = i - a * 150;
                float* d = sm + OFF_STAGE + 7200 + (4 * c) * 12 + a;
                d[0] = v.x; d[12] = v.y; d[24] = v.z; d[36] = v.w;
            }
        }
        __syncthreads();

        const int pr  = tid & 63;      // h-pair: h0 = hf*128 + 2pr, h1 = h0+1
        const int oct = tid >> 6;      // e-octant: 75 e each
        const float2* W2 = reinterpret_cast<const float2*>(enc_w) + (hf * 64 + pr);

        unsigned long long A[20];
        #pragma unroll
        for (int k = 0; k < 20; k++) A[k] = 0ull;

        const float* r0b = sm + OFF_STAGE;
        const float* r1b = sm + OFF_STAGE + 7200;
        const int e0 = oct * 75;
        #pragma unroll 5
        for (int e = e0; e < e0 + 75; e++) {
            float2 w = __ldg(W2 + (size_t)e * (HH / 2));
            unsigned long long wp0 = pack2(w.x);
            unsigned long long wp1 = pack2(w.y);

            const float* r0 = r0b + e * 12;
            const float* r1 = r1b + e * 12;
            ulonglong2 x0 = *reinterpret_cast<const ulonglong2*>(r0);
            ulonglong2 x1 = *reinterpret_cast<const ulonglong2*>(r0 + 4);
            unsigned long long x2 = *reinterpret_cast<const unsigned long long*>(r0 + 8);
            ulonglong2 y0 = *reinterpret_cast<const ulonglong2*>(r1);
            ulonglong2 y1 = *reinterpret_cast<const ulonglong2*>(r1 + 4);
            unsigned long long y2 = *reinterpret_cast<const unsigned long long*>(r1 + 8);

            fma_f32x2(A[0], x0.x, wp0); fma_f32x2(A[1], x0.y, wp0);
            fma_f32x2(A[2], x1.x, wp0); fma_f32x2(A[3], x1.y, wp0);
            fma_f32x2(A[4], x2,   wp0);
            fma_f32x2(A[5], x0.x, wp1); fma_f32x2(A[6], x0.y, wp1);
            fma_f32x2(A[7], x1.x, wp1); fma_f32x2(A[8], x1.y, wp1);
            fma_f32x2(A[9], x2,   wp1);
            fma_f32x2(A[10], y0.x, wp0); fma_f32x2(A[11], y0.y, wp0);
            fma_f32x2(A[12], y1.x, wp0); fma_f32x2(A[13], y1.y, wp0);
            fma_f32x2(A[14], y2,   wp0);
            fma_f32x2(A[15], y0.x, wp1); fma_f32x2(A[16], y0.y, wp1);
            fma_f32x2(A[17], y1.x, wp1); fma_f32x2(A[18], y1.y, wp1);
            fma_f32x2(A[19], y2,   wp1);
        }

        unsigned long long* P = reinterpret_cast<unsigned long long*>(sm + OFF_PART);
        #pragma unroll
        for (int k = 0; k < 20; k++) P[(k * 8 + oct) * 64 + pr] = A[k];
        __syncthreads();

        float* red = sm + OFF_RED;
        if (tid < 256) {
            int pair = tid >> 2, slot = tid & 3;   // slot = jsel*2 + hsel
            int kb = slot * 5;
            int h = hf * 128 + pair * 2 + (slot & 1);
            float eb = enc_b[h];
            float qw = qlin_w[h];
            float s = 0.f;
            #pragma unroll
            for (int k2 = 0; k2 < 5; k2++) {
                float l = 0.f, hv = 0.f;
                #pragma unroll
                for (int oc = 0; oc < 8; oc++) {
                    unsigned long long v = P[((kb + k2) * 8 + oc) * 64 + pair];
                    l  += __uint_as_float((uint32_t)v);
                    hv += __uint_as_float((uint32_t)(v >> 32));
                }
                s += fmaxf(l + eb, 0.f) + fmaxf(hv + eb, 0.f);
            }
            float val = s * qw;
            val += __shfl_xor_sync(0xffffffffu, val, 1);   // fold hsel
            val += __shfl_xor_sync(0xffffffffu, val, 4);   // fold pairs
            val += __shfl_xor_sync(0xffffffffu, val, 8);
            val += __shfl_xor_sync(0xffffffffu, val, 16);
            if (lane == 0) red[wid * 2]     = val;   // jsel 0
            if (lane == 2) red[wid * 2 + 1] = val;   // jsel 1
        }
        __syncthreads();
        if (tid == 0) {
            float sj0 = 0.f, sj1 = 0.f;
            #pragma unroll
            for (int w = 0; w < 8; w++) { sj0 += red[2 * w]; sj1 += red[2 * w + 1]; }
            g_shalf[hf][j0] = sj0;
            g_shalf[hf][j1] = sj1;
        }
    }

    // ================= done barrier + finisher =================
    __threadfence();
    __syncthreads();
    if (tid == 0) {
        unsigned old = atomicAdd(&g_done, 1u);
        bc[1] = (old == GRID - 1) ? 1 : 0;
    }
    __syncthreads();
    if (bc[1]) {
        __threadfence();               // acquire all blocks' results
        // reset state for next graph replay
        if (tid < NJOB) g_flag[tid] = 0u;
        if (tid == 0) { g_pctr = 0u; g_gctr = 0u; g_done = 0u; }

        int fb = wid;                  // warp per batch
        float c0w = cls_w[0], c1w = cls_w[1], c2w = cls_w[2],
              c3w = cls_w[3], c4w = cls_w[4];
        float cb = cls_b[0];
        float qb = qlin_b[0];

        float ml[TN];
        #pragma unroll
        for (int t = 0; t < TN; t++) {
            float eo = elo[fb * TN + t];
            float es = els[fb * TN + t];
            float ca = cate[(fb * TN + t) * 2 + 0];
            float cbv = cate[(fb * TN + t) * 2 + 1];
            float as = g_shalf[0][fb * TN + t] + g_shalf[1][fb * TN + t] + qb;
            float lg = eo * c0w + es * c1w + ca * c2w + cbv * c3w + as * c4w + cb;
            float tm = ((es + eo) != 0.f) ? 1.f : 0.f;
            ml[t] = tm * lg + (1.f - tm) * NEGV;
        }
        if (lane < TN) out[fb * TN + lane] = ml[lane];

        float mx = ml[0];
        #pragma unroll
        for (int t = 1; t < TN; t++) mx = fmaxf(mx, ml[t]);
        float p[TN];
        float sum = 0.f;
        #pragma unroll
        for (int t = 0; t < TN; t++) { p[t] = expf(ml[t] - mx); sum += p[t]; }
        float inv = 1.f / sum;

        float s = 0.f;
        #pragma unroll
        for (int t = 0; t < TN; t++)
            s += p[t] * inv * g_maxat[(fb * TN + t) * QL + lane];

        float m2 = s;
        #pragma unroll
        for (int o = 16; o; o >>= 1) m2 = fmaxf(m2, __shfl_xor_sync(0xffffffffu, m2, o));
        float ex = expf(s - m2);
        float tot = ex;
        #pragma unroll
        for (int o = 16; o; o >>= 1) tot += __shfl_xor_sync(0xffffffffu, tot, o);
        out[BB * TN + fb * QL + lane] = ex / tot;
    }
}

extern "C" void kernel_launch(void* const* d_in, const int* in_sizes, int n_in,
                              void* d_out, int out_size)
{
    const int*   q      = (const int*)  d_in[0];
    const int*   alia   = (const int*)  d_in[1];
    const float* els    = (const float*)d_in[2];
    const float* elo    = (const float*)d_in[3];
    const float* cate   = (const float*)d_in[4];
    const float* emb    = (const float*)d_in[5];
    const float* sim_w  = (const float*)d_in[6];
    const float* sim_b  = (const float*)d_in[7];
    const float* enc_w  = (const float*)d_in[8];
    const float* enc_b  = (const float*)d_in[9];
    const float* qlin_w = (const float*)d_in[10];
    const float* qlin_b = (const float*)d_in[11];
    const float* cls_w  = (const float*)d_in[12];
    const float* cls_b  = (const float*)d_in[13];
    float* out = (float*)d_out;

    cudaFuncSetAttribute(topic_persist, cudaFuncAttributeMaxDynamicSharedMemorySize, SMEM_BYTES);

    topic_persist<<<GRID, 512, SMEM_BYTES>>>(q, alia, els, elo, cate, emb,
                                             sim_w, sim_b, enc_w, enc_b,
                                             qlin_w, qlin_b, cls_w, cls_b, out);
}

// round 9
// speedup vs baseline: 1.0913x; 1.0913x over previous
#include <cuda_runtime.h>
#include <cstdint>

#define BB 16
#define QL 32
#define TN 10
#define AL 10
#define EE 300
#define HH 256
#define NJOB (BB * TN)
#define NPAIR (NJOB / 2)
#define NEGV -10000000000.0f

#define QP 308    // q_emb smem row stride
#define AP 304    // aw3 row stride
#define RS 12     // encT row stride

// ---- smem layout (floats) ----
#define OFF_W     0        // sim_w w1,w2,w3 : 900
#define OFF_QE    900      // q_emb [32][308] = 9856        -> 10756
#define OFF_AW3   10756    // aw3 [2][10][304] = 6080       -> 16836
#define OFF_ENCT  16836    // encT [2][600][12] = 14400     -> 31236
#define OFF_ATT   31236    // atten [2][10][32] = 640       -> 31876
#define OFF_ATTS  31876    // 640                           -> 32516
#define OFF_QW2   32516    // 32
#define OFF_QM    32548    // 32
#define OFF_AW1   32580    // 32 (2x16)
#define OFF_AM    32612    // 32
#define OFF_RED   32644    // 32
#define OFF_FLAG  32676    // 4
#define SMEM_FLOATS 32680
#define SMEM_BYTES (SMEM_FLOATS * 4)
// GEMM partials overlay floats [0, 15360) = W+QE+AW3 region (dead by then)

__device__ float    g_maxat[NJOB * QL];
__device__ float    g_score[NJOB];
__device__ unsigned g_done = 0;

__device__ __forceinline__ void fma_f32x2(unsigned long long& acc,
                                          unsigned long long a,
                                          unsigned long long b)
{
    asm("fma.rn.f32x2 %0, %1, %2, %0;" : "+l"(acc) : "l"(a), "l"(b));
}

__device__ __forceinline__ unsigned long long pack2(float v)
{
    unsigned long long r;
    uint32_t u = __float_as_uint(v);
    asm("mov.b64 %0, {%1, %1};" : "=l"(r) : "r"(u));
    return r;
}

__global__ void __launch_bounds__(1024, 1)
topic_pair(const int* __restrict__ q, const int* __restrict__ alia,
           const float* __restrict__ els, const float* __restrict__ elo,
           const float* __restrict__ cate, const float* __restrict__ emb,
           const float* __restrict__ sim_w, const float* __restrict__ sim_b,
           const float* __restrict__ enc_w, const float* __restrict__ enc_b,
           const float* __restrict__ qlin_w, const float* __restrict__ qlin_b,
           const float* __restrict__ cls_w, const float* __restrict__ cls_b,
           float* __restrict__ out)
{
    extern __shared__ float sm[];
    float* w1      = sm + OFF_W;
    float* w2      = w1 + EE;
    float* w3      = w2 + EE;
    float* q_emb   = sm + OFF_QE;
    float* aw3     = sm + OFF_AW3;     // [js][a][AP]
    float* encT    = sm + OFF_ENCT;    // [js][600][12]
    float* atten   = sm + OFF_ATT;     // [js][a][32]
    float* attensm = sm + OFF_ATTS;
    float* qW2     = sm + OFF_QW2;
    float* qmaskS  = sm + OFF_QM;
    float* aW1     = sm + OFF_AW1;     // [js*16 + a]
    float* amaskS  = sm + OFF_AM;
    float* red     = sm + OFF_RED;

    const int tid  = threadIdx.x;
    const int lane = tid & 31;
    const int wid  = tid >> 5;          // 0..31
    const int jp   = blockIdx.x;        // 0..79
    const int b    = jp / 5;
    const int j0   = b * TN + 2 * (jp % 5);
    const int j1   = j0 + 1;

    const float simb = sim_b[0];

    for (int i = tid; i < 3 * EE; i += 1024) sm[OFF_W + i] = sim_w[i];
    __syncthreads();

    // ---- q rows: 32 warps, one row each ----
    {
        int j = wid;
        int idx = q[b * QL + j];
        float x[10];
        float ss = 0.f;
        #pragma unroll
        for (int i = 0; i < 10; i++) {
            int e = lane + 32 * i;
            float v = (e < EE) ? emb[(size_t)idx * EE + e] : 0.f;
            x[i] = v;
            ss += v * v;
        }
        #pragma unroll
        for (int o = 16; o; o >>= 1) ss += __shfl_xor_sync(0xffffffffu, ss, o);
        float scale = (idx == 0) ? 0.f : 1.f / fmaxf(sqrtf(ss), 1e-12f);
        float dot = 0.f;
        #pragma unroll
        for (int i = 0; i < 10; i++) {
            int e = lane + 32 * i;
            float v = x[i] * scale;
            if (e < EE) {
                q_emb[j * QP + e] = v;
                dot += v * w2[e];
            } else if (e < QP) {
                q_emb[j * QP + e] = 0.f;   // pad [300,308)
            }
        }
        #pragma unroll
        for (int o = 16; o; o >>= 1) dot += __shfl_xor_sync(0xffffffffu, dot, o);
        if (lane == 0) {
            qW2[j]    = dot;
            qmaskS[j] = (idx != 0) ? 1.f : 0.f;
        }
    }

    // ---- alias rows: warps 0..19 = (js, a) ----
    if (wid < 2 * AL) {
        int js = wid / AL, a = wid % AL;
        int job = js ? j1 : j0;
        int idx = alia[job * AL + a];
        float x[10];
        float ss = 0.f;
        #pragma unroll
        for (int i = 0; i < 10; i++) {
            int e = lane + 32 * i;
            float v = (e < EE) ? emb[(size_t)idx * EE + e] : 0.f;
            x[i] = v;
            ss += v * v;
        }
        #pragma unroll
        for (int o = 16; o; o >>= 1) ss += __shfl_xor_sync(0xffffffffu, ss, o);
        float scale = (idx == 0) ? 0.f : 1.f / fmaxf(sqrtf(ss), 1e-12f);
        float dot = 0.f;
        float* awr = aw3 + (js * AL + a) * AP;
        float* ecb = encT + js * 7200;
        #pragma unroll
        for (int i = 0; i < 10; i++) {
            int e = lane + 32 * i;
            float v = x[i] * scale;
            if (e < EE) {
                awr[e] = v * w3[e];
                ecb[(300 + e) * RS + a] = v;
                dot += v * w1[e];
            } else if (e < AP) {
                awr[e] = 0.f;              // pad [300,304)
            }
        }
        #pragma unroll
        for (int o = 16; o; o >>= 1) dot += __shfl_xor_sync(0xffffffffu, dot, o);
        if (lane == 0) {
            aW1[js * 16 + a]    = dot;
            amaskS[js * 16 + a] = (idx != 0) ? 1.f : 0.f;
        }
    }
    __syncthreads();

    // ---- attention: warps 0..19 = (js, a), lane = qi ----
    if (wid < 2 * AL) {
        int js = wid / AL, a = wid % AL, qi = lane;
        const float4* qe = reinterpret_cast<const float4*>(q_emb + qi * QP);
        const float4* ar = reinterpret_cast<const float4*>(aw3 + (js * AL + a) * AP);
        float d = 0.f;
        #pragma unroll 5
        for (int c = 0; c < 75; c++) {
            float4 qv = qe[c];
            float4 av = ar[c];
            d += av.x * qv.x + av.y * qv.y + av.z * qv.z + av.w * qv.w;
        }
        float val = aW1[js * 16 + a] + qW2[qi] + d + simb;
        float m = amaskS[js * 16 + a] * qmaskS[qi];
        atten[js * 320 + a * QL + qi] = m * val + (1.f - m) * NEGV;
    }
    __syncthreads();

    // ---- softmax per (js,a) row + cross-a max per js ----
    if (wid < 2 * AL) {
        int js = wid / AL, a = wid % AL;
        float v = atten[js * 320 + a * QL + lane];
        float mx = v;
        #pragma unroll
        for (int o = 16; o; o >>= 1) mx = fmaxf(mx, __shfl_xor_sync(0xffffffffu, mx, o));
        float ex = expf(v - mx);
        float s = ex;
        #pragma unroll
        for (int o = 16; o; o >>= 1) s += __shfl_xor_sync(0xffffffffu, s, o);
        attensm[js * 320 + a * QL + lane] = ex / s;
    }
    if (wid == 20 || wid == 21) {
        int js = wid - 20;
        float mx = atten[js * 320 + lane];
        #pragma unroll
        for (int a = 1; a < AL; a++) mx = fmaxf(mx, atten[js * 320 + a * QL + lane]);
        g_maxat[(js ? j1 : j0) * QL + lane] = mx;
    }
    __syncthreads();

    // ---- alig -> encT[js] rows 0..299 ----
    for (int p = tid; p < 2 * AL * 75; p += 1024) {
        int js = p / 750, rem = p - js * 750;
        int a = rem / 75, c = rem - a * 75;
        const float* as = attensm + js * 320 + a * QL;
        float4 acc = make_float4(0.f, 0.f, 0.f, 0.f);
        #pragma unroll
        for (int qi = 0; qi < QL; qi++) {
            float s = as[qi];
            float4 qv = *reinterpret_cast<const float4*>(q_emb + qi * QP + c * 4);
            acc.x += s * qv.x; acc.y += s * qv.y; acc.z += s * qv.z; acc.w += s * qv.w;
        }
        float* ecb = encT + js * 7200;
        int e = c * 4;
        ecb[(e + 0) * RS + a] = acc.x;
        ecb[(e + 1) * RS + a] = acc.y;
        ecb[(e + 2) * RS + a] = acc.z;
        ecb[(e + 3) * RS + a] = acc.w;
    }
    __syncthreads();

    // ---- enc GEMM: 128 h-pairs x 4 e-quarters x 2 js ----
    {
        const int pr  = tid & 127;
        const int qtr = (tid >> 7) & 3;
        const int js  = tid >> 9;
        const int e0  = qtr * 150;
        const float2* W2 = reinterpret_cast<const float2*>(enc_w) + pr;
        const float* base = encT + js * 7200;

        unsigned long long A01 = 0ull, A23 = 0ull, A45 = 0ull, A67 = 0ull, A89 = 0ull;
        unsigned long long B01 = 0ull, B23 = 0ull, B45 = 0ull, B67 = 0ull, B89 = 0ull;

        #pragma unroll 2
        for (int e = e0; e < e0 + 150; e++) {
            float2 w = __ldg(W2 + (size_t)e * (HH / 2));
            unsigned long long wp0 = pack2(w.x);
            unsigned long long wp1 = pack2(w.y);

            const ulonglong2* r = reinterpret_cast<const ulonglong2*>(base + e * RS);
            ulonglong2 p0 = r[0];
            ulonglong2 p1 = r[1];
            unsigned long long p2 =
                *reinterpret_cast<const unsigned long long*>(base + e * RS + 8);

            fma_f32x2(A01, p0.x, wp0);
            fma_f32x2(A23, p0.y, wp0);
            fma_f32x2(A45, p1.x, wp0);
            fma_f32x2(A67, p1.y, wp0);
            fma_f32x2(A89, p2,   wp0);

            fma_f32x2(B01, p0.x, wp1);
            fma_f32x2(B23, p0.y, wp1);
            fma_f32x2(B45, p1.x, wp1);
            fma_f32x2(B67, p1.y, wp1);
            fma_f32x2(B89, p2,   wp1);
        }

        __syncthreads();   // W/q_emb/aw3 dead -> overlay partials at sm+0
        unsigned long long* P = reinterpret_cast<unsigned long long*>(sm);
        if (qtr != 0) {
            unsigned long long* dst = P + ((size_t)(js * 3 + qtr - 1) * 128 + pr) * 10;
            dst[0] = A01; dst[1] = A23; dst[2] = A45; dst[3] = A67; dst[4] = A89;
            dst[5] = B01; dst[6] = B23; dst[7] = B45; dst[8] = B67; dst[9] = B89;
        }
        __syncthreads();

        if (qtr == 0) {     // warps 0..3 (js=0) and 16..19 (js=1)
            unsigned long long C[10] = {A01, A23, A45, A67, A89,
                                        B01, B23, B45, B67, B89};
            #pragma unroll
            for (int g = 0; g < 3; g++) {
                const unsigned long long* src = P + ((size_t)(js * 3 + g) * 128 + pr) * 10;
                #pragma unroll
                for (int k = 0; k < 10; k++) {
                    unsigned long long v = src[k];
                    float lo = __uint_as_float((uint32_t)C[k]) + __uint_as_float((uint32_t)v);
                    float hi = __uint_as_float((uint32_t)(C[k] >> 32)) + __uint_as_float((uint32_t)(v >> 32));
                    C[k] = ((unsigned long long)__float_as_uint(hi) << 32) | __float_as_uint(lo);
                }
            }
            float2 eb = *reinterpret_cast<const float2*>(enc_b + 2 * pr);
            float2 qw = *reinterpret_cast<const float2*>(qlin_w + 2 * pr);
            float s0 = 0.f, s1 = 0.f;
            #pragma unroll
            for (int k = 0; k < 5; k++) {
                s0 += fmaxf(__uint_as_float((uint32_t)C[k]) + eb.x, 0.f);
                s0 += fmaxf(__uint_as_float((uint32_t)(C[k] >> 32)) + eb.x, 0.f);
                s1 += fmaxf(__uint_as_float((uint32_t)C[5 + k]) + eb.y, 0.f);
                s1 += fmaxf(__uint_as_float((uint32_t)(C[5 + k] >> 32)) + eb.y, 0.f);
            }
            float val = s0 * qw.x + s1 * qw.y;
            #pragma unroll
            for (int o = 16; o; o >>= 1) val += __shfl_xor_sync(0xffffffffu, val, o);
            if (lane == 0) red[wid] = val;
        }
        __syncthreads();
        if (tid == 0)   g_score[j0] = red[0]  + red[1]  + red[2]  + red[3];
        if (tid == 512) g_score[j1] = red[16] + red[17] + red[18] + red[19];
    }

    // ---- finisher-block: last arriving block computes the finale ----
    __syncthreads();
    if (tid == 0) {
        __threadfence();
        unsigned old = atomicAdd(&g_done, 1u);
        sm[OFF_FLAG] = (old == NPAIR - 1) ? 1.f : 0.f;
    }
    __syncthreads();
    if (sm[OFF_FLAG] != 0.f) {
        __threadfence();
        if (tid == 0) g_done = 0;

        if (wid < BB) {
            int fb = wid;
            float c0w = cls_w[0], c1w = cls_w[1], c2w = cls_w[2],
                  c3w = cls_w[3], c4w = cls_w[4];
            float cb = cls_b[0];
            float qb = qlin_b[0];

            float ml[TN];
            #pragma unroll
            for (int t = 0; t < TN; t++) {
                float eo = elo[fb * TN + t];
                float es = els[fb * TN + t];
                float ca = cate[(fb * TN + t) * 2 + 0];
                float cbv = cate[(fb * TN + t) * 2 + 1];
                float as = g_score[fb * TN + t] + qb;
                float lg = eo * c0w + es * c1w + ca * c2w + cbv * c3w + as * c4w + cb;
                float tm = ((es + eo) != 0.f) ? 1.f : 0.f;
                ml[t] = tm * lg + (1.f - tm) * NEGV;
            }
            if (lane < TN) out[fb * TN + lane] = ml[lane];

            float mx = ml[0];
            #pragma unroll
            for (int t = 1; t < TN; t++) mx = fmaxf(mx, ml[t]);
            float p[TN];
            float sum = 0.f;
            #pragma unroll
            for (int t = 0; t < TN; t++) { p[t] = expf(ml[t] - mx); sum += p[t]; }
            float inv = 1.f / sum;

            float s = 0.f;
            #pragma unroll
            for (int t = 0; t < TN; t++)
                s += p[t] * inv * g_maxat[(fb * TN + t) * QL + lane];

            float m2 = s;
            #pragma unroll
            for (int o = 16; o; o >>= 1) m2 = fmaxf(m2, __shfl_xor_sync(0xffffffffu, m2, o));
            float ex = expf(s - m2);
            float tot = ex;
            #pragma unroll
            for (int o = 16; o; o >>= 1) tot += __shfl_xor_sync(0xffffffffu, tot, o);
            out[BB * TN + fb * QL + lane] = ex / tot;
        }
    }
}

extern "C" void kernel_launch(void* const* d_in, const int* in_sizes, int n_in,
                              void* d_out, int out_size)
{
    const int*   q      = (const int*)  d_in[0];
    const int*   alia   = (const int*)  d_in[1];
    const float* els    = (const float*)d_in[2];
    const float* elo    = (const float*)d_in[3];
    const float* cate   = (const float*)d_in[4];
    const float* emb    = (const float*)d_in[5];
    const float* sim_w  = (const float*)d_in[6];
    const float* sim_b  = (const float*)d_in[7];
    const float* enc_w  = (const float*)d_in[8];
    const float* enc_b  = (const float*)d_in[9];
    const float* qlin_w = (const float*)d_in[10];
    const float* qlin_b = (const float*)d_in[11];
    const float* cls_w  = (const float*)d_in[12];
    const float* cls_b  = (const float*)d_in[13];
    float* out = (float*)d_out;

    cudaFuncSetAttribute(topic_pair, cudaFuncAttributeMaxDynamicSharedMemorySize, SMEM_BYTES);

    topic_pair<<<NPAIR, 1024, SMEM_BYTES>>>(q, alia, els, elo, cate, emb,
                                            sim_w, sim_b, enc_w, enc_b,
                                            qlin_w, qlin_b, cls_w, cls_b, out);
}